// round 16
// baseline (speedup 1.0000x reference)
#include <cuda_runtime.h>
#include <cuda_fp16.h>
#include <cstdint>
#include <math.h>

#define T_ 4
#define B_ 8
#define C_ 256
#define HID_ 1024
#define E_ 8
#define K_ 2
#define HW_ 196
#define NPIX_ 784   /* T_*HW_ */
#define EPS_ 1e-5f

// ======================= helpers =======================
__device__ __forceinline__ uint32_t smem_u32(const void* p) {
    uint32_t a;
    asm("{ .reg .u64 t; cvta.to.shared.u64 t, %1; cvt.u32.u64 %0, t; }" : "=r"(a) : "l"(p));
    return a;
}
__device__ __forceinline__ void cp_async16(uint32_t saddr, const void* gptr) {
    asm volatile("cp.async.cg.shared.global [%0], [%1], 16;" :: "r"(saddr), "l"(gptr) : "memory");
}
__device__ __forceinline__ void ldsm_x4(uint32_t& r0, uint32_t& r1, uint32_t& r2, uint32_t& r3,
                                        uint32_t addr) {
    asm volatile("ldmatrix.sync.aligned.m8n8.x4.shared.b16 {%0,%1,%2,%3}, [%4];"
                 : "=r"(r0), "=r"(r1), "=r"(r2), "=r"(r3) : "r"(addr));
}
__device__ __forceinline__ void mma_f16(float* c, const uint32_t* a, const uint32_t* b) {
    asm volatile("mma.sync.aligned.m16n8k16.row.col.f32.f16.f16.f32 "
                 "{%0,%1,%2,%3}, {%4,%5,%6,%7}, {%8,%9}, {%0,%1,%2,%3};"
                 : "+f"(c[0]), "+f"(c[1]), "+f"(c[2]), "+f"(c[3])
                 : "r"(a[0]), "r"(a[1]), "r"(a[2]), "r"(a[3]), "r"(b[0]), "r"(b[1]));
}
__device__ __forceinline__ void red_add_f32(float* gptr, float v) {
    asm volatile("red.global.add.f32 [%0], %1;" :: "l"(gptr), "f"(v) : "memory");
}

// ======================= device scratch (static) =======================
__device__ __align__(128) __half g_W1s[2u * E_ * HID_ * C_];     // [split][e][m][k]
__device__ __align__(128) __half g_W2s[1u * E_ * C_ * HID_];     // [e][m][k] (hi only)
__device__ __align__(128) __half g_S1T[16u * NPIX_ * C_];        // [slot][n][c]
__device__ __align__(128) __half g_S2T[16u * NPIX_ * HID_];      // [slot][n][k]
__device__ float g_X[B_ * C_];
__device__ int   g_topi[B_ * K_];
__device__ float g_topw[B_ * K_];

// ======================= prep (W splits) + reduce_x + out=x init, one launch =============
__global__ void prep_reduce_kernel(const float* __restrict__ w1, const float* __restrict__ w2,
                                   const float* __restrict__ x, float* __restrict__ out) {
    const int NW = E_ * HID_ * C_;           // 2,097,152 each
    const int PREP_BLOCKS = 2 * NW / 1024;   // 4096
    const int RED_BLOCKS = B_ * C_;          // 2048
    int bx = blockIdx.x;
    if (bx < PREP_BLOCKS) {
        int i4 = (bx * 256 + threadIdx.x) * 4;
        if (i4 < NW) {
            float4 wv = *(const float4*)(w1 + i4);
            float w[4] = {wv.x, wv.y, wv.z, wv.w};
            uint16_t h[4], m[4];
#pragma unroll
            for (int j = 0; j < 4; j++) {
                __half hi = __float2half(w[j]);
                __half mi = __float2half(w[j] - __half2float(hi));
                h[j] = __half_as_ushort(hi);
                m[j] = __half_as_ushort(mi);
            }
            *(uint2*)&g_W1s[i4] = make_uint2((uint32_t)h[0] | ((uint32_t)h[1] << 16),
                                             (uint32_t)h[2] | ((uint32_t)h[3] << 16));
            *(uint2*)&g_W1s[NW + i4] = make_uint2((uint32_t)m[0] | ((uint32_t)m[1] << 16),
                                                  (uint32_t)m[2] | ((uint32_t)m[3] << 16));
        } else {
            int idx = i4 - NW;
            float4 wv = *(const float4*)(w2 + idx);
            float w[4] = {wv.x, wv.y, wv.z, wv.w};
            uint16_t h[4];
#pragma unroll
            for (int j = 0; j < 4; j++) h[j] = __half_as_ushort(__float2half(w[j]));
            *(uint2*)&g_W2s[idx] = make_uint2((uint32_t)h[0] | ((uint32_t)h[1] << 16),
                                              (uint32_t)h[2] | ((uint32_t)h[3] << 16));
        }
    } else if (bx < PREP_BLOCKS + RED_BLOCKS) {
        int bc = bx - PREP_BLOCKS;           // b*C_ + c
        int b = bc / C_, c = bc % C_;
        float s = 0.f;
        for (int idx = threadIdx.x; idx < T_ * HW_; idx += 256) {
            int t = idx / HW_, hw = idx % HW_;
            s += x[((size_t)(t * B_ + b) * C_ + c) * HW_ + hw];
        }
        __shared__ float red[8];
        for (int o = 16; o; o >>= 1) s += __shfl_down_sync(0xFFFFFFFFu, s, o);
        if ((threadIdx.x & 31) == 0) red[threadIdx.x >> 5] = s;
        __syncthreads();
        if (threadIdx.x == 0) {
            float tot = 0.f;
#pragma unroll
            for (int j = 0; j < 8; j++) tot += red[j];
            g_X[bc] = tot / (float)(T_ * HW_);
        }
    } else {
        // out = x (residual pre-fill; mma2 red.adds the moe term)
        int i = ((bx - PREP_BLOCKS - RED_BLOCKS) * 256 + threadIdx.x) * 4;
        *(float4*)(out + i) = *(const float4*)(x + i);
    }
}

// ======================= router =======================
__global__ void router_kernel(const float* __restrict__ rw, const float* __restrict__ rb,
                              const float* __restrict__ bg, const float* __restrict__ bb,
                              const float* __restrict__ bm, const float* __restrict__ bv) {
    __shared__ float lg[B_][E_];
    int tid = threadIdx.x;
    int b = tid / E_, e = tid % E_;
    float dot = 0.f;
    for (int c = 0; c < C_; c++) dot += rw[e * C_ + c] * g_X[b * C_ + c];
    float val = dot + rb[e];
    float sc = bg[e] / sqrtf(bv[e] + EPS_);
    lg[b][e] = (val - bm[e]) * sc + bb[e];
    __syncthreads();
    if (tid < B_) {
        float best = -1e30f, sec = -1e30f; int bi = 0, si = 0;
        for (int ee = 0; ee < E_; ee++) {
            float p = lg[tid][ee];
            if (p > best)     { sec = best; si = bi; best = p; bi = ee; }
            else if (p > sec) { sec = p; si = ee; }
        }
        float r = expf(sec - best);
        g_topi[tid * K_ + 0] = bi; g_topw[tid * K_ + 0] = 1.f / (1.f + r);
        g_topi[tid * K_ + 1] = si; g_topw[tid * K_ + 1] = r / (1.f + r);
    }
}

// ======================= spike1: x -> S1T fp16 [slot][n=hw*4+t][c], 2 slots/block ========
__global__ void spike1_kernel(const float* __restrict__ x, const float* __restrict__ taus) {
    __shared__ __half ss[2][32][116];
    int b = blockIdx.z, hw0 = blockIdx.y * 28, c0 = blockIdx.x * 32;
    float tau0 = taus[g_topi[2 * b]];
    float tau1 = taus[g_topi[2 * b + 1]];
    int tid = threadIdx.x;
    const size_t TSTRIDE = (size_t)B_ * C_ * HW_;
    for (int p = tid; p < 32 * 28; p += 256) {
        int cl = p / 28, hwl = p - cl * 28;
        const float* xp = x + ((size_t)(b * C_) + c0 + cl) * HW_ + hw0 + hwl;
        float xt[4];
#pragma unroll
        for (int t = 0; t < T_; t++) xt[t] = xp[t * TSTRIDE];
        float v0 = 0.f, v1 = 0.f;
#pragma unroll
        for (int t = 0; t < T_; t++) {
            float h0 = v0 + (xt[t] - v0) / tau0;
            float s0 = (h0 >= 1.0f) ? 1.f : 0.f;
            ss[0][cl][hwl * 4 + t] = __float2half(s0);
            v0 = h0 * (1.f - s0);
            float h1 = v1 + (xt[t] - v1) / tau1;
            float s1 = (h1 >= 1.0f) ? 1.f : 0.f;
            ss[1][cl][hwl * 4 + t] = __float2half(s1);
            v1 = h1 * (1.f - s1);
        }
    }
    __syncthreads();
    for (int q = tid; q < 2 * 112 * 8; q += 256) {
        int sl = q / 896, r = q - sl * 896, nl = r >> 3, pa = r & 7;
        uint2 w;
        w.x = (uint32_t)__half_as_ushort(ss[sl][pa * 4 + 0][nl])
            | ((uint32_t)__half_as_ushort(ss[sl][pa * 4 + 1][nl]) << 16);
        w.y = (uint32_t)__half_as_ushort(ss[sl][pa * 4 + 2][nl])
            | ((uint32_t)__half_as_ushort(ss[sl][pa * 4 + 3][nl]) << 16);
        *(uint2*)&g_S1T[((size_t)(2 * b + sl) * NPIX_ + hw0 * 4 + nl) * C_ + c0 + pa * 4] = w;
    }
}

// ======================= mma1: 128x112 tile, BK=32, 3-stage (R13 proven) =================
__global__ __launch_bounds__(256, 2)
void mma1_kernel(const float* __restrict__ bias,
                 const float* __restrict__ bng, const float* __restrict__ bnb,
                 const float* __restrict__ bnm, const float* __restrict__ bnv,
                 const float* __restrict__ taus) {
    constexpr int NIT = C_ / 32;              // 8
    constexpr int STAGE = 2 * 10240 + 8960;   // 29440
    extern __shared__ __align__(16) char smem[];
    uint32_t sbase = smem_u32(smem);

    int tid = threadIdx.x, lane = tid & 31, wid = tid >> 5;
    int warpM = wid >> 1, warpN = wid & 1;
    int slot = blockIdx.z, m0 = blockIdx.y * 128, n0 = blockIdx.x * 112;
    int e = g_topi[slot];

    const __half* Wbase = g_W1s;
    const __half* Bbase = g_S1T + (size_t)slot * NPIX_ * C_ + (size_t)n0 * C_;

    uint32_t agoff[4], asoff[4];
#pragma unroll
    for (int j = 0; j < 4; j++) {
        int q = tid + 256 * j;
        int sp = q >> 9, r = (q >> 2) & 127, cu = q & 3;
        agoff[j] = (uint32_t)(((sp * E_ + e) * HID_ + m0 + r) * C_ + cu * 8);
        asoff[j] = sp * 10240 + r * 80 + cu * 16;
    }
    uint32_t bgoff[2], bsoff[2];
#pragma unroll
    for (int j = 0; j < 2; j++) {
        int q = tid + 256 * j;
        bgoff[j] = (uint32_t)((q >> 2) * C_ + (q & 3) * 8);
        bsoff[j] = 2 * 10240 + (q >> 2) * 80 + (q & 3) * 16;
    }
    const bool bact1 = (tid + 256) < 448;

    uint32_t bw0 = sbase + 2 * 10240
                 + (warpN * 56 + (lane & 7)) * 80 + ((lane >> 3) & 1) * 16
                 + (lane >> 4) * 32;
    uint32_t aw0 = sbase + (warpM * 32 + (lane & 15)) * 80 + (lane >> 4) * 16;

    float acc[2][7][4];
#pragma unroll
    for (int mt = 0; mt < 2; mt++)
#pragma unroll
        for (int nt = 0; nt < 7; nt++)
#pragma unroll
            for (int cc = 0; cc < 4; cc++) acc[mt][nt][cc] = 0.f;

    auto load_stage = [&](int st, int kc) {
        uint32_t sb = sbase + st * STAGE;
        int ko = kc * 32;
#pragma unroll
        for (int j = 0; j < 4; j++)
            cp_async16(sb + asoff[j], Wbase + agoff[j] + ko);
        cp_async16(sb + bsoff[0], Bbase + bgoff[0] + ko);
        if (bact1) cp_async16(sb + bsoff[1], Bbase + bgoff[1] + ko);
        asm volatile("cp.async.commit_group;" ::: "memory");
    };

    load_stage(0, 0);
    load_stage(1, 1);

    for (int i = 0; i < NIT; i++) {
        if (i + 1 < NIT) asm volatile("cp.async.wait_group 1;" ::: "memory");
        else             asm volatile("cp.async.wait_group 0;" ::: "memory");
        __syncthreads();
        uint32_t stoff = (i % 3) * STAGE;

        uint32_t b[7][4];
#pragma unroll
        for (int nt = 0; nt < 7; nt++)
            ldsm_x4(b[nt][0], b[nt][1], b[nt][2], b[nt][3], bw0 + stoff + nt * 640);

        if (i + 2 < NIT) load_stage((i + 2) % 3, i + 2);

#pragma unroll
        for (int sp = 0; sp < 2; sp++) {
            uint32_t abase = aw0 + stoff + sp * 10240;
#pragma unroll
            for (int kst = 0; kst < 2; kst++) {
                uint32_t a[2][4];
                ldsm_x4(a[0][0], a[0][1], a[0][2], a[0][3], abase + kst * 32);
                ldsm_x4(a[1][0], a[1][1], a[1][2], a[1][3], abase + 16 * 80 + kst * 32);
#pragma unroll
                for (int nt = 0; nt < 7; nt++) {
                    mma_f16(acc[0][nt], a[0], &b[nt][kst * 2]);
                    mma_f16(acc[1][nt], a[1], &b[nt][kst * 2]);
                }
            }
        }
    }

    // ---- epilogue: bn1 + LIF -> smem transpose -> coalesced S2T rows ----
    int rb = lane >> 2, q = lane & 3;
    float tau = taus[e];
    __half* sE = (__half*)smem;               // [112 n][pitch 136] halves
    __syncthreads();

#pragma unroll
    for (int mt = 0; mt < 2; mt++)
#pragma unroll
        for (int h = 0; h < 2; h++) {
            int ml = warpM * 32 + mt * 16 + h * 8 + rb;
            int eo = e * HID_ + m0 + ml;
            float sc  = bng[eo] / sqrtf(bnv[eo] + EPS_);
            float off = (bias[eo] - bnm[eo]) * sc + bnb[eo];
#pragma unroll
            for (int nt = 0; nt < 7; nt++) {
                float x0 = acc[mt][nt][h * 2 + 0] * sc + off;
                float x1 = acc[mt][nt][h * 2 + 1] * sc + off;
                float h0 = x0 / tau;
                float s0 = (h0 >= 1.f) ? 1.f : 0.f;
                float v1 = h0 * (1.f - s0);
                float h1 = v1 + (x1 - v1) / tau;
                float s1 = (h1 >= 1.f) ? 1.f : 0.f;
                float vA = h1 * (1.f - s1);
                float vin = __shfl_sync(0xFFFFFFFFu, vA, lane & ~1);
                float h2 = vin + (x0 - vin) / tau;
                float s2 = (h2 >= 1.f) ? 1.f : 0.f;
                float v3 = h2 * (1.f - s2);
                float h3 = v3 + (x1 - v3) / tau;
                float s3 = (h3 >= 1.f) ? 1.f : 0.f;
                float o0 = (q & 1) ? s2 : s0;
                float o1 = (q & 1) ? s3 : s1;
                int nl = warpN * 56 + nt * 8 + q * 2;
                sE[nl * 136 + ml]       = __float2half(o0);
                sE[(nl + 1) * 136 + ml] = __float2half(o1);
            }
        }
    __syncthreads();
    for (int p = tid; p < 112 * 16; p += 256) {
        int nl = p >> 4, u = p & 15;
        uint4 v = *(uint4*)((char*)sE + nl * 272 + u * 16);
        *(uint4*)&g_S2T[((size_t)slot * NPIX_ + n0 + nl) * HID_ + m0 + u * 8] = v;
    }
}

// ======================= mma2: 128x112 tile, BK=64, 3-stage; red.add epilogue ============
__global__ __launch_bounds__(256, 2)
void mma2_kernel(float* __restrict__ out,
                 const float* __restrict__ bias,
                 const float* __restrict__ bng, const float* __restrict__ bnb,
                 const float* __restrict__ bnm, const float* __restrict__ bnv) {
    constexpr int NIT = HID_ / 64;            // 16
    constexpr int BOFF = 128 * 144;           // 18432
    constexpr int STAGE = BOFF + 112 * 144;   // 34560
    extern __shared__ __align__(16) char smem[];
    uint32_t sbase = smem_u32(smem);

    int tid = threadIdx.x, lane = tid & 31, wid = tid >> 5;
    int warpM = wid >> 1, warpN = wid & 1;
    int slot = blockIdx.z, m0 = blockIdx.y * 128, n0 = blockIdx.x * 112;
    int e = g_topi[slot];

    const __half* Wbase = g_W2s;
    const __half* Bbase = g_S2T + ((size_t)slot * NPIX_ + n0) * HID_;

    uint32_t agoff[4], asoff[4], bgoff[4], bsoff[4];
#pragma unroll
    for (int j = 0; j < 4; j++) {
        int q = tid + 256 * j;
        int r = q >> 3, cu = q & 7;
        agoff[j] = (uint32_t)((e * C_ + m0 + r) * HID_ + cu * 8);
        asoff[j] = r * 144 + cu * 16;
        bgoff[j] = (uint32_t)(r * HID_ + cu * 8);
        bsoff[j] = BOFF + r * 144 + cu * 16;
    }
    const bool bact3 = (tid + 768) < 896;

    uint32_t bw0 = sbase + BOFF
                 + (warpN * 56 + (lane & 7)) * 144 + ((lane >> 3) & 1) * 16
                 + (lane >> 4) * 32;
    uint32_t aw0 = sbase + (warpM * 32 + (lane & 15)) * 144 + (lane >> 4) * 16;

    float acc[2][7][4];
#pragma unroll
    for (int mt = 0; mt < 2; mt++)
#pragma unroll
        for (int nt = 0; nt < 7; nt++)
#pragma unroll
            for (int cc = 0; cc < 4; cc++) acc[mt][nt][cc] = 0.f;

    auto load_stage = [&](int st, int kc) {
        uint32_t sb = sbase + st * STAGE;
        int ko = kc * 64;
#pragma unroll
        for (int j = 0; j < 4; j++)
            cp_async16(sb + asoff[j], Wbase + agoff[j] + ko);
#pragma unroll
        for (int j = 0; j < 3; j++)
            cp_async16(sb + bsoff[j], Bbase + bgoff[j] + ko);
        if (bact3) cp_async16(sb + bsoff[3], Bbase + bgoff[3] + ko);
        asm volatile("cp.async.commit_group;" ::: "memory");
    };

    load_stage(0, 0);
    load_stage(1, 1);

    for (int i = 0; i < NIT; i++) {
        if (i + 1 < NIT) asm volatile("cp.async.wait_group 1;" ::: "memory");
        else             asm volatile("cp.async.wait_group 0;" ::: "memory");
        __syncthreads();
        uint32_t stoff = (i % 3) * STAGE;

#pragma unroll
        for (int half = 0; half < 2; half++) {
            uint32_t b[7][4];
#pragma unroll
            for (int nt = 0; nt < 7; nt++)
                ldsm_x4(b[nt][0], b[nt][1], b[nt][2], b[nt][3],
                        bw0 + stoff + nt * 1152 + half * 64);
            if (half == 0 && i + 2 < NIT) load_stage((i + 2) % 3, i + 2);
#pragma unroll
            for (int kst = 0; kst < 2; kst++) {
                uint32_t a[2][4];
                ldsm_x4(a[0][0], a[0][1], a[0][2], a[0][3],
                        aw0 + stoff + half * 64 + kst * 32);
                ldsm_x4(a[1][0], a[1][1], a[1][2], a[1][3],
                        aw0 + stoff + 16 * 144 + half * 64 + kst * 32);
#pragma unroll
                for (int nt = 0; nt < 7; nt++) {
                    mma_f16(acc[0][nt], a[0], &b[nt][kst * 2]);
                    mma_f16(acc[1][nt], a[1], &b[nt][kst * 2]);
                }
            }
        }
    }

    // ---- epilogue: bn2*topw -> sP transpose -> red.add into out (residual pre-filled) ----
    int rb = lane >> 2, q = lane & 3;
    float w = g_topw[slot];
    int b = slot >> 1;
    float* sP = (float*)smem;                 // [128 m][pitch 113] fp32
    __syncthreads();
#pragma unroll
    for (int mt = 0; mt < 2; mt++)
#pragma unroll
        for (int h = 0; h < 2; h++) {
            int ml = warpM * 32 + mt * 16 + h * 8 + rb;
            int eo = e * C_ + m0 + ml;
            float bnsc = bng[eo] / sqrtf(bnv[eo] + EPS_);
            float scw = bnsc * w;
            float offw = ((bias[eo] - bnm[eo]) * bnsc + bnb[eo]) * w;
#pragma unroll
            for (int nt = 0; nt < 7; nt++) {
#pragma unroll
                for (int col = 0; col < 2; col++) {
                    int nl = warpN * 56 + nt * 8 + q * 2 + col;
                    sP[ml * 113 + nl] = acc[mt][nt][h * 2 + col] * scw + offw;
                }
            }
        }
    __syncthreads();
    int hw0 = blockIdx.x * 28;
    for (int p = tid; p < 512; p += 256) {
        int m = p >> 2, t = p & 3;
        float* dst = out + ((size_t)(t * B_ + b) * C_ + m0 + m) * HW_ + hw0;
        const float* srow = sP + m * 113 + t;
#pragma unroll
        for (int hwl = 0; hwl < 28; hwl++) red_add_f32(dst + hwl, srow[hwl * 4]);
    }
}

// ======================= launch =======================
extern "C" void kernel_launch(void* const* d_in, const int* in_sizes, int n_in,
                              void* d_out, int out_size) {
    const float* x        = (const float*)d_in[0];
    const float* router_w = (const float*)d_in[1];
    const float* router_b = (const float*)d_in[2];
    const float* rbn_g    = (const float*)d_in[3];
    const float* rbn_b    = (const float*)d_in[4];
    const float* rbn_m    = (const float*)d_in[5];
    const float* rbn_v    = (const float*)d_in[6];
    const float* fc1_w    = (const float*)d_in[7];
    const float* fc1_b    = (const float*)d_in[8];
    const float* bn1_g    = (const float*)d_in[9];
    const float* bn1_b    = (const float*)d_in[10];
    const float* bn1_m    = (const float*)d_in[11];
    const float* bn1_v    = (const float*)d_in[12];
    const float* fc2_w    = (const float*)d_in[13];
    const float* fc2_b    = (const float*)d_in[14];
    const float* bn2_g    = (const float*)d_in[15];
    const float* bn2_b    = (const float*)d_in[16];
    const float* bn2_m    = (const float*)d_in[17];
    const float* bn2_v    = (const float*)d_in[18];
    const float* taus     = (const float*)d_in[19];
    float* out = (float*)d_out;

    const int SMEM1 = 3 * (2 * 10240 + 8960);              // 88320
    const int SMEM2 = 3 * 34560;                           // 103680
    cudaFuncSetAttribute(mma1_kernel, cudaFuncAttributeMaxDynamicSharedMemorySize, SMEM1);
    cudaFuncSetAttribute(mma2_kernel, cudaFuncAttributeMaxDynamicSharedMemorySize, SMEM2);

    const int TOTAL_BLOCKS = 2 * E_ * HID_ * C_ / 1024 + B_ * C_
                           + T_ * B_ * C_ * HW_ / 1024;    // 4096 + 2048 + 1568
    prep_reduce_kernel<<<TOTAL_BLOCKS, 256>>>(fc1_w, fc2_w, x, out);
    router_kernel<<<1, 64>>>(router_w, router_b, rbn_g, rbn_b, rbn_m, rbn_v);
    spike1_kernel<<<dim3(C_ / 32, 7, B_), 256>>>(x, taus);
    mma1_kernel<<<dim3(7, HID_ / 128, B_ * K_), 256, SMEM1>>>(
        fc1_b, bn1_g, bn1_b, bn1_m, bn1_v, taus);
    mma2_kernel<<<dim3(7, C_ / 128, B_ * K_), 256, SMEM2>>>(
        out, fc2_b, bn2_g, bn2_b, bn2_m, bn2_v);
}

// round 17
// speedup vs baseline: 1.0871x; 1.0871x over previous
#include <cuda_runtime.h>
#include <cuda_fp16.h>
#include <cstdint>
#include <math.h>

#define T_ 4
#define B_ 8
#define C_ 256
#define HID_ 1024
#define E_ 8
#define K_ 2
#define HW_ 196
#define NPIX_ 784   /* T_*HW_ */
#define EPS_ 1e-5f

// ======================= helpers =======================
__device__ __forceinline__ uint32_t smem_u32(const void* p) {
    uint32_t a;
    asm("{ .reg .u64 t; cvta.to.shared.u64 t, %1; cvt.u32.u64 %0, t; }" : "=r"(a) : "l"(p));
    return a;
}
__device__ __forceinline__ void cp_async16(uint32_t saddr, const void* gptr) {
    asm volatile("cp.async.cg.shared.global [%0], [%1], 16;" :: "r"(saddr), "l"(gptr) : "memory");
}
__device__ __forceinline__ void ldsm_x4(uint32_t& r0, uint32_t& r1, uint32_t& r2, uint32_t& r3,
                                        uint32_t addr) {
    asm volatile("ldmatrix.sync.aligned.m8n8.x4.shared.b16 {%0,%1,%2,%3}, [%4];"
                 : "=r"(r0), "=r"(r1), "=r"(r2), "=r"(r3) : "r"(addr));
}
__device__ __forceinline__ void mma_f16(float* c, const uint32_t* a, const uint32_t* b) {
    asm volatile("mma.sync.aligned.m16n8k16.row.col.f32.f16.f16.f32 "
                 "{%0,%1,%2,%3}, {%4,%5,%6,%7}, {%8,%9}, {%0,%1,%2,%3};"
                 : "+f"(c[0]), "+f"(c[1]), "+f"(c[2]), "+f"(c[3])
                 : "r"(a[0]), "r"(a[1]), "r"(a[2]), "r"(a[3]), "r"(b[0]), "r"(b[1]));
}

// ======================= device scratch (static) =======================
__device__ __align__(128) __half g_W1s[2u * E_ * HID_ * C_];     // [split][e][m][k]
__device__ __align__(128) __half g_W2s[1u * E_ * C_ * HID_];     // [e][m][k] (hi only)
__device__ __align__(128) __half g_S1T[16u * NPIX_ * C_];        // [slot][n][c]
__device__ __align__(128) __half g_S2T[16u * NPIX_ * HID_];      // [slot][n][k]
__device__ __align__(128) float  g_O  [16u * C_ * NPIX_];        // [slot][c][t][hw]
__device__ float g_X[B_ * C_];
__device__ int   g_topi[B_ * K_];
__device__ float g_topw[B_ * K_];

// ======================= prep (W splits) + reduce_x fused =======================
__global__ void prep_reduce_kernel(const float* __restrict__ w1, const float* __restrict__ w2,
                                   const float* __restrict__ x) {
    const int NW = E_ * HID_ * C_;    // 2,097,152 each
    const int PREP_BLOCKS = 2 * NW / 1024;   // 4096
    if (blockIdx.x < PREP_BLOCKS) {
        int i4 = (blockIdx.x * 256 + threadIdx.x) * 4;
        if (i4 < NW) {
            float4 wv = *(const float4*)(w1 + i4);
            float w[4] = {wv.x, wv.y, wv.z, wv.w};
            uint16_t h[4], m[4];
#pragma unroll
            for (int j = 0; j < 4; j++) {
                __half hi = __float2half(w[j]);
                __half mi = __float2half(w[j] - __half2float(hi));
                h[j] = __half_as_ushort(hi);
                m[j] = __half_as_ushort(mi);
            }
            *(uint2*)&g_W1s[i4] = make_uint2((uint32_t)h[0] | ((uint32_t)h[1] << 16),
                                             (uint32_t)h[2] | ((uint32_t)h[3] << 16));
            *(uint2*)&g_W1s[NW + i4] = make_uint2((uint32_t)m[0] | ((uint32_t)m[1] << 16),
                                                  (uint32_t)m[2] | ((uint32_t)m[3] << 16));
        } else {
            int idx = i4 - NW;
            float4 wv = *(const float4*)(w2 + idx);
            float w[4] = {wv.x, wv.y, wv.z, wv.w};
            uint16_t h[4];
#pragma unroll
            for (int j = 0; j < 4; j++) h[j] = __half_as_ushort(__float2half(w[j]));
            *(uint2*)&g_W2s[idx] = make_uint2((uint32_t)h[0] | ((uint32_t)h[1] << 16),
                                              (uint32_t)h[2] | ((uint32_t)h[3] << 16));
        }
    } else {
        int bc = blockIdx.x - PREP_BLOCKS;    // b*C_ + c
        int b = bc / C_, c = bc % C_;
        float s = 0.f;
        for (int idx = threadIdx.x; idx < T_ * HW_; idx += 256) {
            int t = idx / HW_, hw = idx % HW_;
            s += x[((size_t)(t * B_ + b) * C_ + c) * HW_ + hw];
        }
        __shared__ float red[8];
        for (int o = 16; o; o >>= 1) s += __shfl_down_sync(0xFFFFFFFFu, s, o);
        if ((threadIdx.x & 31) == 0) red[threadIdx.x >> 5] = s;
        __syncthreads();
        if (threadIdx.x == 0) {
            float tot = 0.f;
#pragma unroll
            for (int j = 0; j < 8; j++) tot += red[j];
            g_X[bc] = tot / (float)(T_ * HW_);
        }
    }
}

// ======================= spike1 + inlined router (per-block, deterministic) ==============
// Each block computes the top-2 for its batch b from g_X, then does its spike tile.
__global__ void spike1_kernel(const float* __restrict__ x, const float* __restrict__ taus,
                              const float* __restrict__ rw, const float* __restrict__ rb,
                              const float* __restrict__ bg, const float* __restrict__ bb,
                              const float* __restrict__ bm, const float* __restrict__ bv) {
    __shared__ __half ss[2][32][116];
    __shared__ float lgp[E_][8];              // per-expert partials
    __shared__ float s_tau[2];
    int b = blockIdx.z, hw0 = blockIdx.y * 28, c0 = blockIdx.x * 32;
    int tid = threadIdx.x;

    // ---- router: 64 threads, 8 partials per expert, fixed-order reduce ----
    if (tid < 64) {
        int e = tid >> 3, part = tid & 7;
        float s = 0.f;
        const float* rwp = rw + e * C_ + part * 32;
        const float* xp  = g_X + b * C_ + part * 32;
#pragma unroll
        for (int c = 0; c < 32; c++) s += rwp[c] * xp[c];
        lgp[e][part] = s;
    }
    __syncthreads();
    if (tid == 0) {
        float best = -1e30f, sec = -1e30f; int bi = 0, si = 0;
#pragma unroll
        for (int e = 0; e < E_; e++) {
            float dot = 0.f;
#pragma unroll
            for (int j = 0; j < 8; j++) dot += lgp[e][j];
            float sc = bg[e] / sqrtf(bv[e] + EPS_);
            float p = (dot + rb[e] - bm[e]) * sc + bb[e];
            if (p > best)     { sec = best; si = bi; best = p; bi = e; }
            else if (p > sec) { sec = p; si = e; }
        }
        float r = expf(sec - best);
        g_topi[b * K_ + 0] = bi; g_topw[b * K_ + 0] = 1.f / (1.f + r);
        g_topi[b * K_ + 1] = si; g_topw[b * K_ + 1] = r / (1.f + r);
        s_tau[0] = taus[bi]; s_tau[1] = taus[si];
    }
    __syncthreads();
    float tau0 = s_tau[0], tau1 = s_tau[1];

    const size_t TSTRIDE = (size_t)B_ * C_ * HW_;
    for (int p = tid; p < 32 * 28; p += 256) {
        int cl = p / 28, hwl = p - cl * 28;
        const float* xp = x + ((size_t)(b * C_) + c0 + cl) * HW_ + hw0 + hwl;
        float xt[4];
#pragma unroll
        for (int t = 0; t < T_; t++) xt[t] = xp[t * TSTRIDE];
        float v0 = 0.f, v1 = 0.f;
#pragma unroll
        for (int t = 0; t < T_; t++) {
            float h0 = v0 + (xt[t] - v0) / tau0;
            float s0 = (h0 >= 1.0f) ? 1.f : 0.f;
            ss[0][cl][hwl * 4 + t] = __float2half(s0);
            v0 = h0 * (1.f - s0);
            float h1 = v1 + (xt[t] - v1) / tau1;
            float s1 = (h1 >= 1.0f) ? 1.f : 0.f;
            ss[1][cl][hwl * 4 + t] = __float2half(s1);
            v1 = h1 * (1.f - s1);
        }
    }
    __syncthreads();
    for (int q = tid; q < 2 * 112 * 8; q += 256) {
        int sl = q / 896, r = q - sl * 896, nl = r >> 3, pa = r & 7;
        uint2 w;
        w.x = (uint32_t)__half_as_ushort(ss[sl][pa * 4 + 0][nl])
            | ((uint32_t)__half_as_ushort(ss[sl][pa * 4 + 1][nl]) << 16);
        w.y = (uint32_t)__half_as_ushort(ss[sl][pa * 4 + 2][nl])
            | ((uint32_t)__half_as_ushort(ss[sl][pa * 4 + 3][nl]) << 16);
        *(uint2*)&g_S1T[((size_t)(2 * b + sl) * NPIX_ + hw0 * 4 + nl) * C_ + c0 + pa * 4] = w;
    }
}

// ======================= mma1: 128x112 tile, BK=32, 3-stage (R13 proven) =================
__global__ __launch_bounds__(256, 2)
void mma1_kernel(const float* __restrict__ bias,
                 const float* __restrict__ bng, const float* __restrict__ bnb,
                 const float* __restrict__ bnm, const float* __restrict__ bnv,
                 const float* __restrict__ taus) {
    constexpr int NIT = C_ / 32;              // 8
    constexpr int STAGE = 2 * 10240 + 8960;   // 29440
    extern __shared__ __align__(16) char smem[];
    uint32_t sbase = smem_u32(smem);

    int tid = threadIdx.x, lane = tid & 31, wid = tid >> 5;
    int warpM = wid >> 1, warpN = wid & 1;
    int slot = blockIdx.z, m0 = blockIdx.y * 128, n0 = blockIdx.x * 112;
    int e = g_topi[slot];

    const __half* Wbase = g_W1s;
    const __half* Bbase = g_S1T + (size_t)slot * NPIX_ * C_ + (size_t)n0 * C_;

    uint32_t agoff[4], asoff[4];
#pragma unroll
    for (int j = 0; j < 4; j++) {
        int q = tid + 256 * j;
        int sp = q >> 9, r = (q >> 2) & 127, cu = q & 3;
        agoff[j] = (uint32_t)(((sp * E_ + e) * HID_ + m0 + r) * C_ + cu * 8);
        asoff[j] = sp * 10240 + r * 80 + cu * 16;
    }
    uint32_t bgoff[2], bsoff[2];
#pragma unroll
    for (int j = 0; j < 2; j++) {
        int q = tid + 256 * j;
        bgoff[j] = (uint32_t)((q >> 2) * C_ + (q & 3) * 8);
        bsoff[j] = 2 * 10240 + (q >> 2) * 80 + (q & 3) * 16;
    }
    const bool bact1 = (tid + 256) < 448;

    uint32_t bw0 = sbase + 2 * 10240
                 + (warpN * 56 + (lane & 7)) * 80 + ((lane >> 3) & 1) * 16
                 + (lane >> 4) * 32;
    uint32_t aw0 = sbase + (warpM * 32 + (lane & 15)) * 80 + (lane >> 4) * 16;

    float acc[2][7][4];
#pragma unroll
    for (int mt = 0; mt < 2; mt++)
#pragma unroll
        for (int nt = 0; nt < 7; nt++)
#pragma unroll
            for (int cc = 0; cc < 4; cc++) acc[mt][nt][cc] = 0.f;

    auto load_stage = [&](int st, int kc) {
        uint32_t sb = sbase + st * STAGE;
        int ko = kc * 32;
#pragma unroll
        for (int j = 0; j < 4; j++)
            cp_async16(sb + asoff[j], Wbase + agoff[j] + ko);
        cp_async16(sb + bsoff[0], Bbase + bgoff[0] + ko);
        if (bact1) cp_async16(sb + bsoff[1], Bbase + bgoff[1] + ko);
        asm volatile("cp.async.commit_group;" ::: "memory");
    };

    load_stage(0, 0);
    load_stage(1, 1);

    for (int i = 0; i < NIT; i++) {
        if (i + 1 < NIT) asm volatile("cp.async.wait_group 1;" ::: "memory");
        else             asm volatile("cp.async.wait_group 0;" ::: "memory");
        __syncthreads();
        uint32_t stoff = (i % 3) * STAGE;

        uint32_t b[7][4];
#pragma unroll
        for (int nt = 0; nt < 7; nt++)
            ldsm_x4(b[nt][0], b[nt][1], b[nt][2], b[nt][3], bw0 + stoff + nt * 640);

        if (i + 2 < NIT) load_stage((i + 2) % 3, i + 2);

#pragma unroll
        for (int sp = 0; sp < 2; sp++) {
            uint32_t abase = aw0 + stoff + sp * 10240;
#pragma unroll
            for (int kst = 0; kst < 2; kst++) {
                uint32_t a[2][4];
                ldsm_x4(a[0][0], a[0][1], a[0][2], a[0][3], abase + kst * 32);
                ldsm_x4(a[1][0], a[1][1], a[1][2], a[1][3], abase + 16 * 80 + kst * 32);
#pragma unroll
                for (int nt = 0; nt < 7; nt++) {
                    mma_f16(acc[0][nt], a[0], &b[nt][kst * 2]);
                    mma_f16(acc[1][nt], a[1], &b[nt][kst * 2]);
                }
            }
        }
    }

    // ---- epilogue: bn1 + LIF -> smem transpose -> coalesced S2T rows ----
    int rb = lane >> 2, q = lane & 3;
    float tau = taus[e];
    __half* sE = (__half*)smem;               // [112 n][pitch 136] halves
    __syncthreads();

#pragma unroll
    for (int mt = 0; mt < 2; mt++)
#pragma unroll
        for (int h = 0; h < 2; h++) {
            int ml = warpM * 32 + mt * 16 + h * 8 + rb;
            int eo = e * HID_ + m0 + ml;
            float sc  = bng[eo] / sqrtf(bnv[eo] + EPS_);
            float off = (bias[eo] - bnm[eo]) * sc + bnb[eo];
#pragma unroll
            for (int nt = 0; nt < 7; nt++) {
                float x0 = acc[mt][nt][h * 2 + 0] * sc + off;
                float x1 = acc[mt][nt][h * 2 + 1] * sc + off;
                float h0 = x0 / tau;
                float s0 = (h0 >= 1.f) ? 1.f : 0.f;
                float v1 = h0 * (1.f - s0);
                float h1 = v1 + (x1 - v1) / tau;
                float s1 = (h1 >= 1.f) ? 1.f : 0.f;
                float vA = h1 * (1.f - s1);
                float vin = __shfl_sync(0xFFFFFFFFu, vA, lane & ~1);
                float h2 = vin + (x0 - vin) / tau;
                float s2 = (h2 >= 1.f) ? 1.f : 0.f;
                float v3 = h2 * (1.f - s2);
                float h3 = v3 + (x1 - v3) / tau;
                float s3 = (h3 >= 1.f) ? 1.f : 0.f;
                float o0 = (q & 1) ? s2 : s0;
                float o1 = (q & 1) ? s3 : s1;
                int nl = warpN * 56 + nt * 8 + q * 2;
                sE[nl * 136 + ml]       = __float2half(o0);
                sE[(nl + 1) * 136 + ml] = __float2half(o1);
            }
        }
    __syncthreads();
    for (int p = tid; p < 112 * 16; p += 256) {
        int nl = p >> 4, u = p & 15;
        uint4 v = *(uint4*)((char*)sE + nl * 272 + u * 16);
        *(uint4*)&g_S2T[((size_t)slot * NPIX_ + n0 + nl) * HID_ + m0 + u * 8] = v;
    }
}

// ======================= mma2: 128x112 tile, BK=64, 3-stage, NIT=16 ======================
__global__ __launch_bounds__(256, 2)
void mma2_kernel(const float* __restrict__ bias,
                 const float* __restrict__ bng, const float* __restrict__ bnb,
                 const float* __restrict__ bnm, const float* __restrict__ bnv) {
    constexpr int NIT = HID_ / 64;            // 16
    constexpr int BOFF = 128 * 144;           // 18432
    constexpr int STAGE = BOFF + 112 * 144;   // 34560
    extern __shared__ __align__(16) char smem[];
    uint32_t sbase = smem_u32(smem);

    int tid = threadIdx.x, lane = tid & 31, wid = tid >> 5;
    int warpM = wid >> 1, warpN = wid & 1;
    int slot = blockIdx.z, m0 = blockIdx.y * 128, n0 = blockIdx.x * 112;
    int e = g_topi[slot];

    const __half* Wbase = g_W2s;
    const __half* Bbase = g_S2T + ((size_t)slot * NPIX_ + n0) * HID_;

    uint32_t agoff[4], asoff[4], bgoff[4], bsoff[4];
#pragma unroll
    for (int j = 0; j < 4; j++) {
        int q = tid + 256 * j;
        int r = q >> 3, cu = q & 7;
        agoff[j] = (uint32_t)((e * C_ + m0 + r) * HID_ + cu * 8);
        asoff[j] = r * 144 + cu * 16;
        bgoff[j] = (uint32_t)(r * HID_ + cu * 8);
        bsoff[j] = BOFF + r * 144 + cu * 16;
    }
    const bool bact3 = (tid + 768) < 896;

    uint32_t bw0 = sbase + BOFF
                 + (warpN * 56 + (lane & 7)) * 144 + ((lane >> 3) & 1) * 16
                 + (lane >> 4) * 32;
    uint32_t aw0 = sbase + (warpM * 32 + (lane & 15)) * 144 + (lane >> 4) * 16;

    float acc[2][7][4];
#pragma unroll
    for (int mt = 0; mt < 2; mt++)
#pragma unroll
        for (int nt = 0; nt < 7; nt++)
#pragma unroll
            for (int cc = 0; cc < 4; cc++) acc[mt][nt][cc] = 0.f;

    auto load_stage = [&](int st, int kc) {
        uint32_t sb = sbase + st * STAGE;
        int ko = kc * 64;
#pragma unroll
        for (int j = 0; j < 4; j++)
            cp_async16(sb + asoff[j], Wbase + agoff[j] + ko);
#pragma unroll
        for (int j = 0; j < 3; j++)
            cp_async16(sb + bsoff[j], Bbase + bgoff[j] + ko);
        if (bact3) cp_async16(sb + bsoff[3], Bbase + bgoff[3] + ko);
        asm volatile("cp.async.commit_group;" ::: "memory");
    };

    load_stage(0, 0);
    load_stage(1, 1);

    for (int i = 0; i < NIT; i++) {
        if (i + 1 < NIT) asm volatile("cp.async.wait_group 1;" ::: "memory");
        else             asm volatile("cp.async.wait_group 0;" ::: "memory");
        __syncthreads();
        uint32_t stoff = (i % 3) * STAGE;

#pragma unroll
        for (int half = 0; half < 2; half++) {
            uint32_t b[7][4];
#pragma unroll
            for (int nt = 0; nt < 7; nt++)
                ldsm_x4(b[nt][0], b[nt][1], b[nt][2], b[nt][3],
                        bw0 + stoff + nt * 1152 + half * 64);
            if (half == 0 && i + 2 < NIT) load_stage((i + 2) % 3, i + 2);
#pragma unroll
            for (int kst = 0; kst < 2; kst++) {
                uint32_t a[2][4];
                ldsm_x4(a[0][0], a[0][1], a[0][2], a[0][3],
                        aw0 + stoff + half * 64 + kst * 32);
                ldsm_x4(a[1][0], a[1][1], a[1][2], a[1][3],
                        aw0 + stoff + 16 * 144 + half * 64 + kst * 32);
#pragma unroll
                for (int nt = 0; nt < 7; nt++) {
                    mma_f16(acc[0][nt], a[0], &b[nt][kst * 2]);
                    mma_f16(acc[1][nt], a[1], &b[nt][kst * 2]);
                }
            }
        }
    }

    // ---- epilogue: bn2*topw -> sP transpose -> g_O coalesced ----
    int rb = lane >> 2, q = lane & 3;
    float w = g_topw[slot];
    float* sP = (float*)smem;                 // [128 m][pitch 113] fp32
    __syncthreads();
#pragma unroll
    for (int mt = 0; mt < 2; mt++)
#pragma unroll
        for (int h = 0; h < 2; h++) {
            int ml = warpM * 32 + mt * 16 + h * 8 + rb;
            int eo = e * C_ + m0 + ml;
            float bnsc = bng[eo] / sqrtf(bnv[eo] + EPS_);
            float scw = bnsc * w;
            float offw = ((bias[eo] - bnm[eo]) * bnsc + bnb[eo]) * w;
#pragma unroll
            for (int nt = 0; nt < 7; nt++) {
#pragma unroll
                for (int col = 0; col < 2; col++) {
                    int nl = warpN * 56 + nt * 8 + q * 2 + col;
                    sP[ml * 113 + nl] = acc[mt][nt][h * 2 + col] * scw + offw;
                }
            }
        }
    __syncthreads();
    int hw0 = blockIdx.x * 28;
    for (int p = tid; p < 512; p += 256) {
        int m = p >> 2, t = p & 3;
        float* dst = g_O + ((size_t)((slot * C_ + m0 + m) * 4 + t)) * HW_ + hw0;
        const float* srow = sP + m * 113 + t;
#pragma unroll
        for (int hwl = 0; hwl < 28; hwl++) dst[hwl] = srow[hwl * 4];
    }
}

// ======================= combine (float4) =======================
__global__ void combine_kernel(const float* __restrict__ x, float* __restrict__ out) {
    int i4 = blockIdx.x * 256 + threadIdx.x;
    int i = i4 * 4;
    int hw = i % HW_;
    int c  = (i / HW_) % C_;
    int b  = (i / (HW_ * C_)) % B_;
    int t  = i / (HW_ * C_ * B_);
    size_t o0 = ((size_t)(b * K_) * C_ + c) * NPIX_ + t * HW_ + hw;
    float4 xv = *(const float4*)(x + i);
    float4 a  = *(const float4*)(g_O + o0);
    float4 bq = *(const float4*)(g_O + o0 + (size_t)C_ * NPIX_);
    float4 r;
    r.x = xv.x + a.x + bq.x; r.y = xv.y + a.y + bq.y;
    r.z = xv.z + a.z + bq.z; r.w = xv.w + a.w + bq.w;
    *(float4*)(out + i) = r;
}

// ======================= launch =======================
extern "C" void kernel_launch(void* const* d_in, const int* in_sizes, int n_in,
                              void* d_out, int out_size) {
    const float* x        = (const float*)d_in[0];
    const float* router_w = (const float*)d_in[1];
    const float* router_b = (const float*)d_in[2];
    const float* rbn_g    = (const float*)d_in[3];
    const float* rbn_b    = (const float*)d_in[4];
    const float* rbn_m    = (const float*)d_in[5];
    const float* rbn_v    = (const float*)d_in[6];
    const float* fc1_w    = (const float*)d_in[7];
    const float* fc1_b    = (const float*)d_in[8];
    const float* bn1_g    = (const float*)d_in[9];
    const float* bn1_b    = (const float*)d_in[10];
    const float* bn1_m    = (const float*)d_in[11];
    const float* bn1_v    = (const float*)d_in[12];
    const float* fc2_w    = (const float*)d_in[13];
    const float* fc2_b    = (const float*)d_in[14];
    const float* bn2_g    = (const float*)d_in[15];
    const float* bn2_b    = (const float*)d_in[16];
    const float* bn2_m    = (const float*)d_in[17];
    const float* bn2_v    = (const float*)d_in[18];
    const float* taus     = (const float*)d_in[19];
    float* out = (float*)d_out;

    const int SMEM1 = 3 * (2 * 10240 + 8960);              // 88320
    const int SMEM2 = 3 * 34560;                           // 103680
    cudaFuncSetAttribute(mma1_kernel, cudaFuncAttributeMaxDynamicSharedMemorySize, SMEM1);
    cudaFuncSetAttribute(mma2_kernel, cudaFuncAttributeMaxDynamicSharedMemorySize, SMEM2);

    prep_reduce_kernel<<<2 * E_ * HID_ * C_ / 1024 + B_ * C_, 256>>>(fc1_w, fc2_w, x);
    spike1_kernel<<<dim3(C_ / 32, 7, B_), 256>>>(x, taus, router_w, router_b,
                                                 rbn_g, rbn_b, rbn_m, rbn_v);
    mma1_kernel<<<dim3(7, HID_ / 128, B_ * K_), 256, SMEM1>>>(
        fc1_b, bn1_g, bn1_b, bn1_m, bn1_v, taus);
    mma2_kernel<<<dim3(7, C_ / 128, B_ * K_), 256, SMEM2>>>(
        fc2_b, bn2_g, bn2_b, bn2_m, bn2_v);
    combine_kernel<<<T_ * B_ * C_ * HW_ / 1024, 256>>>(x, out);
}